// round 17
// baseline (speedup 1.0000x reference)
#include <cuda_runtime.h>
#include <cstdint>

typedef unsigned long long u64;

#define N_TOKENS  131072
#define NUM_CODES 1024
#define CODE_DIM  64
#define DECAY     0.99f
#define OMD       0.01f
#define EPS       1e-5f

#define OUT_Q     0
#define OUT_IDX   (N_TOKENS * CODE_DIM)
#define OUT_LOSS  (OUT_IDX + N_TOKENS)
#define OUT_CB    (OUT_LOSS + 1)
#define OUT_CS    (OUT_CB + NUM_CODES * CODE_DIM)
#define OUT_EMA   (OUT_CS + NUM_CODES)

// smem layout (bytes) — R10 champion layout
#define SM_ZS     0                 // 64 d-rows x 128 tokens x 4B = 32768
#define SM_C0     32768             // code tile buf0: 64 x 272 = 17408
#define SM_C1     50176             // code tile buf1: 17408
#define SM_CNS    67584             // 1024 floats = 4096
#define SM_SIDX   71680             // 128 int
#define SM_SBEST  72192             // 128 float
#define SMEM_BYTES 72704

// ---------------- device scratch ----------------
__device__ __align__(16) u64 g_cbp[16 * 64 * 32];  // [chunk][dim][pair] packed code pairs
__device__ float g_dw[NUM_CODES * CODE_DIM];
__device__ float g_counts[NUM_CODES];
__device__ float g_cnorm[NUM_CODES];
__device__ float g_inv[NUM_CODES];
__device__ float g_loss;

// ---------------- helpers ----------------
__device__ __forceinline__ uint32_t smem_u32(const void* p) {
    uint32_t a;
    asm("{ .reg .u64 t; cvta.to.shared.u64 t, %1; cvt.u32.u64 %0, t; }" : "=r"(a) : "l"(p));
    return a;
}
__device__ __forceinline__ u64 pk2(float x, float y) {
    u64 r; asm("mov.b64 %0, {%1, %2};" : "=l"(r) : "f"(x), "f"(y)); return r;
}
__device__ __forceinline__ void upk2(u64 v, float& x, float& y) {
    asm("mov.b64 {%0, %1}, %2;" : "=f"(x), "=f"(y) : "l"(v));
}
__device__ __forceinline__ u64 fma2(u64 a, u64 b, u64 c) {
    u64 r; asm("fma.rn.f32x2 %0, %1, %2, %3;" : "=l"(r) : "l"(a), "l"(b), "l"(c)); return r;
}
__device__ __forceinline__ void cpa16(uint32_t dst, const void* src) {
    asm volatile("cp.async.cg.shared.global [%0], [%1], 16;" :: "r"(dst), "l"(src));
}
#define CP_COMMIT() asm volatile("cp.async.commit_group;" ::: "memory")
#define CP_WAIT1()  asm volatile("cp.async.wait_group 1;" ::: "memory")
#define CP_WAIT0()  asm volatile("cp.async.wait_group 0;" ::: "memory")

// ---------------- prep kernels (assign at launch position 3 for ncu) ----------------
__global__ void prep_zero_a_kernel() {
    int i = blockIdx.x * 256 + threadIdx.x;   // 8192 -> lower half of g_dw
    ((float4*)g_dw)[i] = make_float4(0.f, 0.f, 0.f, 0.f);
    if (i < NUM_CODES) g_counts[i] = 0.0f;
}

__global__ void prep_cb_kernel(const float* __restrict__ cb) {
    int i = blockIdx.x * 256 + threadIdx.x;   // 32768 threads
    int c = i >> 11, r = i & 2047;
    int d = r >> 5, p = r & 31;
    int k0 = c * 64 + 2 * p;
    g_cbp[i] = pk2(cb[(size_t)k0 * 64 + d], cb[(size_t)(k0 + 1) * 64 + d]);
    if (i < NUM_CODES) {
        float s = 0.0f;
        const float4* cr = (const float4*)(cb + (size_t)i * 64);
#pragma unroll
        for (int j = 0; j < 16; j++) {
            float4 w = cr[j];
            s += w.x * w.x + w.y * w.y + w.z * w.z + w.w * w.w;
        }
        g_cnorm[i] = s;
    }
}

__global__ void prep_zero_b_kernel() {
    int i = blockIdx.x * 256 + threadIdx.x;   // 8192 -> upper half of g_dw
    ((float4*)g_dw)[8192 + i] = make_float4(0.f, 0.f, 0.f, 0.f);
    if (i == 0) g_loss = 0.0f;
}

// ---------------- assign: f32x2 GEMM, 8 tok x 8 codes, shfl-exchanged operands ----------------
// 128 threads, 128 tokens/CTA, 1024 CTAs, 3 CTAs/SM.
// cg = tid&7, tgrp = tid>>3.
// Per dim per thread: 1 LDS.128 z (4 tokens, half picked by cg&1) + 4 shfl.xor(1),
//                     1 LDS.128 codes (2 pairs, half picked by tgrp&1) + 2 u64 shfl.xor(8).
__global__ void __launch_bounds__(128, 3)
assign_kernel(const float4* __restrict__ z4, const float4* __restrict__ cb4,
              float* __restrict__ out) {
    extern __shared__ __align__(16) char smem[];
    float* cns   = (float*)(smem + SM_CNS);
    int*   sidx  = (int*)(smem + SM_SIDX);
    float* sbest = (float*)(smem + SM_SBEST);

    const int tid  = threadIdx.x;
    const int cg   = tid & 7;
    const int tgrp = tid >> 3;           // 0..15, owns tokens tgrp*8..tgrp*8+7
    const int t1   = tgrp & 1;           // code-half selector
    const int c1   = cg & 1;             // z-half selector
    const int base = blockIdx.x * 128;
    const uint32_t sbase = smem_u32(smem);

    // ---- stage z: thread owns token tid; zs[d][t] plain f32 (512B rows)
    {
        const float4* zsrc = z4 + (size_t)(base + tid) * 16;
#pragma unroll
        for (int j = 0; j < 16; j++) {
            float4 v = zsrc[j];
            *(float*)(smem + SM_ZS + (4 * j + 0) * 512 + tid * 4) = v.x;
            *(float*)(smem + SM_ZS + (4 * j + 1) * 512 + tid * 4) = v.y;
            *(float*)(smem + SM_ZS + (4 * j + 2) * 512 + tid * 4) = v.z;
            *(float*)(smem + SM_ZS + (4 * j + 3) * 512 + tid * 4) = v.w;
        }
    }
    // ---- resident code norms
#pragma unroll
    for (int i = 0; i < 8; i++) cns[tid + i * 128] = g_cnorm[tid + i * 128];

    // ---- cp.async prologue: chunk 0 -> buf0
    {
        const char* src = (const char*)g_cbp;
#pragma unroll
        for (int i = 0; i < 8; i++) {
            int l = tid + i * 128;
            int d = l >> 4, p = (l & 15) * 2;
            cpa16(sbase + SM_C0 + d * 272 + p * 8 + ((p >> 4) << 4), src + (size_t)l * 16);
        }
        CP_COMMIT();
    }

    float best[8];
    int   bidx[8];
#pragma unroll
    for (int t = 0; t < 8; t++) { best[t] = 3.0e38f; bidx[t] = 0; }
    const u64 NEG2 = pk2(-2.0f, -2.0f);

    // own-half byte offsets (within a dim row)
    // codes: own pair P0 = 4cg + 2*t1 -> byte = P0*8 + ((P0>>4)<<4) = cg*32 + ((cg&4)<<2) + (t1<<4)
    const uint32_t c_off = cg * 32 + ((cg & 4) << 2) + (t1 << 4);
    // z: own 4 tokens start at tgrp*8 + 4*c1 -> byte = tgrp*32 + (c1<<4)
    const uint32_t z_off = tgrp * 32 + (c1 << 4);

    for (int c = 0; c < 16; c++) {
        __syncthreads();   // prior compute done with the buffer being refilled
        if (c < 15) {
            const char* src = (const char*)(g_cbp + (size_t)(c + 1) * 2048);
            uint32_t boff = ((c + 1) & 1) ? SM_C1 : SM_C0;
#pragma unroll
            for (int i = 0; i < 8; i++) {
                int l = tid + i * 128;
                int d = l >> 4, p = (l & 15) * 2;
                cpa16(sbase + boff + d * 272 + p * 8 + ((p >> 4) << 4), src + (size_t)l * 16);
            }
            CP_COMMIT();
            CP_WAIT1();    // chunk c complete
        } else {
            CP_WAIT0();
        }
        __syncthreads();   // chunk c visible

        const char* cbuf = smem + ((c & 1) ? SM_C1 : SM_C0);
        const char* crb  = cbuf + c_off;
        const char* zrb  = smem + SM_ZS + z_off;

        u64 acc[32];
#pragma unroll
        for (int i = 0; i < 32; i++) acc[i] = 0ull;

#pragma unroll 8
        for (int d = 0; d < 64; d++) {
            // own halves: one LDS.128 each, distinct addresses across the warp
            float4      zo = *(const float4*)(zrb + d * 512);
            ulonglong2  co = *(const ulonglong2*)(crb + d * 272);
            // partner halves via shuffle (z: cg^1 -> xor 1; codes: tgrp^1 -> xor 8)
            float zs0 = __shfl_xor_sync(0xffffffffu, zo.x, 1);
            float zs1 = __shfl_xor_sync(0xffffffffu, zo.y, 1);
            float zs2 = __shfl_xor_sync(0xffffffffu, zo.z, 1);
            float zs3 = __shfl_xor_sync(0xffffffffu, zo.w, 1);
            u64 cc2 = __shfl_xor_sync(0xffffffffu, co.x, 8);
            u64 cc3 = __shfl_xor_sync(0xffffffffu, co.y, 8);
            u64 cc0 = co.x, cc1 = co.y;
            u64 zz0 = pk2(zo.x, zo.x), zz1 = pk2(zo.y, zo.y);
            u64 zz2 = pk2(zo.z, zo.z), zz3 = pk2(zo.w, zo.w);
            u64 zz4 = pk2(zs0, zs0),   zz5 = pk2(zs1, zs1);
            u64 zz6 = pk2(zs2, zs2),   zz7 = pk2(zs3, zs3);
            acc[0]  = fma2(zz0, cc0, acc[0]);
            acc[1]  = fma2(zz0, cc1, acc[1]);
            acc[2]  = fma2(zz0, cc2, acc[2]);
            acc[3]  = fma2(zz0, cc3, acc[3]);
            acc[4]  = fma2(zz1, cc0, acc[4]);
            acc[5]  = fma2(zz1, cc1, acc[5]);
            acc[6]  = fma2(zz1, cc2, acc[6]);
            acc[7]  = fma2(zz1, cc3, acc[7]);
            acc[8]  = fma2(zz2, cc0, acc[8]);
            acc[9]  = fma2(zz2, cc1, acc[9]);
            acc[10] = fma2(zz2, cc2, acc[10]);
            acc[11] = fma2(zz2, cc3, acc[11]);
            acc[12] = fma2(zz3, cc0, acc[12]);
            acc[13] = fma2(zz3, cc1, acc[13]);
            acc[14] = fma2(zz3, cc2, acc[14]);
            acc[15] = fma2(zz3, cc3, acc[15]);
            acc[16] = fma2(zz4, cc0, acc[16]);
            acc[17] = fma2(zz4, cc1, acc[17]);
            acc[18] = fma2(zz4, cc2, acc[18]);
            acc[19] = fma2(zz4, cc3, acc[19]);
            acc[20] = fma2(zz5, cc0, acc[20]);
            acc[21] = fma2(zz5, cc1, acc[21]);
            acc[22] = fma2(zz5, cc2, acc[22]);
            acc[23] = fma2(zz5, cc3, acc[23]);
            acc[24] = fma2(zz6, cc0, acc[24]);
            acc[25] = fma2(zz6, cc1, acc[25]);
            acc[26] = fma2(zz6, cc2, acc[26]);
            acc[27] = fma2(zz6, cc3, acc[27]);
            acc[28] = fma2(zz7, cc0, acc[28]);
            acc[29] = fma2(zz7, cc1, acc[29]);
            acc[30] = fma2(zz7, cc2, acc[30]);
            acc[31] = fma2(zz7, cc3, acc[31]);
        }

        // ---- epilogue: acc[t*4+q] is (token-slot t) x (code pair pq)
        //      pq = 4cg + 2*((q>>1) ^ t1) + (q&1); codes = 2pq, 2pq+1
        const int kb = c * 64;
#pragma unroll
        for (int q = 0; q < 4; q++) {
            int p = 4 * cg + 2 * (((q >> 1)) ^ t1) + (q & 1);
            u64 cnp = *(const u64*)&cns[kb + 2 * p];
            int idx0 = kb + 2 * p;
#pragma unroll
            for (int t = 0; t < 8; t++) {
                u64 sp = fma2(acc[t * 4 + q], NEG2, cnp);
                float s0, s1;
                upk2(sp, s0, s1);
                if (s0 < best[t]) { best[t] = s0; bidx[t] = idx0; }
                if (s1 < best[t]) { best[t] = s1; bidx[t] = idx0 + 1; }
            }
        }
    }

    // ---- fix token-slot order: odd cg accumulated tokens [4..7] in slots [0..3]
    if (c1) {
#pragma unroll
        for (int t = 0; t < 4; t++) {
            float tv = best[t]; best[t] = best[t + 4]; best[t + 4] = tv;
            int   ti = bidx[t]; bidx[t] = bidx[t + 4]; bidx[t + 4] = ti;
        }
    }

    // ---- cross-lane argmin over 8 cg lanes (lane bits 0..2), tie-break lowest index
#pragma unroll
    for (int t = 0; t < 8; t++) {
        float v = best[t];
        int   i = bidx[t];
#pragma unroll
        for (int off = 1; off <= 4; off <<= 1) {
            float ov = __shfl_xor_sync(0xffffffffu, v, off);
            int   oi = __shfl_xor_sync(0xffffffffu, i, off);
            if (ov < v || (ov == v && oi < i)) { v = ov; i = oi; }
        }
        if (cg == 0) { sidx[tgrp * 8 + t] = i; sbest[tgrp * 8 + t] = v; }
    }
    __syncthreads();

    // ---- scatter: thread owns token tid (z from smem, conflict-free)
    {
        int idx = sidx[tid];
        int tok = base + tid;
        out[OUT_IDX + tok] = (float)idx;
        atomicAdd(&g_counts[idx], 1.0f);
        float zn = 0.0f;
        float* dwp = &g_dw[idx * 64];
#pragma unroll 8
        for (int d = 0; d < 64; d++) {
            float zv = *(const float*)(smem + SM_ZS + d * 512 + tid * 4);
            zn += zv * zv;
            atomicAdd(&dwp[d], zv);
        }
        float lp = zn + sbest[tid];   // exact d2min
#pragma unroll
        for (int off = 16; off > 0; off >>= 1)
            lp += __shfl_down_sync(0xffffffffu, lp, off);
        if ((tid & 31) == 0) atomicAdd(&g_loss, lp);
    }

    // ---- quantized: cooperative coalesced gather
    float4* outq = (float4*)out;   // OUT_Q == 0
#pragma unroll
    for (int i = 0; i < 16; i++) {
        int l = tid + i * 128;
        int t = l >> 4, j = l & 15;
        outq[(size_t)(base + t) * 16 + j] = cb4[(size_t)sidx[t] * 16 + j];
    }
}

// ---------------- finalize A: per-code stats + loss ----------------
__global__ void finalize_a_kernel(const float* __restrict__ cs_in,
                                  float* __restrict__ out) {
    __shared__ float s[1024];
    int k = threadIdx.x;
    float ncs = DECAY * cs_in[k] + OMD * g_counts[k];
    s[k] = ncs;
    __syncthreads();
    for (int st = 512; st > 0; st >>= 1) {
        if (k < st) s[k] += s[k + st];
        __syncthreads();
    }
    float n   = s[0];
    float csk = (ncs + EPS) / (n + NUM_CODES * EPS) * n;
    out[OUT_CS + k] = ncs;
    g_inv[k] = 1.0f / csk;
    if (k == 0) out[OUT_LOSS] = g_loss * (1.0f / (float)(N_TOKENS * CODE_DIM));
}

// ---------------- finalize B: parallel EMA + codebook update ----------------
__global__ void finalize_b_kernel(const float* __restrict__ ema_in,
                                  float* __restrict__ out) {
    int i = blockIdx.x * 256 + threadIdx.x;   // 65536 threads
    float e = DECAY * ema_in[i] + OMD * g_dw[i];
    out[OUT_EMA + i] = e;
    out[OUT_CB + i]  = e * g_inv[i >> 6];
}

extern "C" void kernel_launch(void* const* d_in, const int* in_sizes, int n_in,
                              void* d_out, int out_size) {
    const float* z   = (const float*)d_in[0];
    const float* cb  = (const float*)d_in[1];
    const float* cs  = (const float*)d_in[2];
    const float* ema = (const float*)d_in[3];
    float* out = (float*)d_out;

    static int smem_set = 0;
    if (!smem_set) {
        cudaFuncSetAttribute(assign_kernel,
                             cudaFuncAttributeMaxDynamicSharedMemorySize, SMEM_BYTES);
        smem_set = 1;
    }

    prep_zero_a_kernel<<<32, 256>>>();                                   // pos 0
    prep_cb_kernel<<<128, 256>>>(cb);                                    // pos 1
    prep_zero_b_kernel<<<32, 256>>>();                                   // pos 2
    assign_kernel<<<1024, 128, SMEM_BYTES>>>((const float4*)z,           // pos 3
                                             (const float4*)cb, out);
    finalize_a_kernel<<<1, 1024>>>(cs, out);                             // pos 4
    finalize_b_kernel<<<256, 256>>>(ema, out);                           // pos 5
}